// round 12
// baseline (speedup 1.0000x reference)
#include <cuda_runtime.h>

#define NELE    8388608
#define HALF    (NELE/2)
#define THREADS 256
#define NWARP   8
#define ITEMS   16
#define TILE    4096          // THREADS*ITEMS
#define NBLK    2048          // NELE/TILE
#define RDX     256
#define WCHUNK  512           // TILE/NWARP
#define PADW    10

#define PT      256
#define PI      16
#define PTILE   4096
#define PNB     1024          // HALF/PTILE

// ---- scratch (device globals; no runtime allocation allowed) ----
__device__ unsigned long long g_bufA[NELE];
__device__ unsigned long long g_bufB[NELE];
__device__ float              g_sp[NELE];
__device__ unsigned int       g_hist[RDX * NBLK];
__device__ unsigned int       g_digTot[RDX];
__device__ unsigned int       g_digBase[RDX];
__device__ double             g_bsP[PNB];
__device__ double             g_bsM[PNB];
__device__ double             g_bt[PNB];

// Radix key: ascending order of (-target) == descending target, IEEE total order.
__device__ __forceinline__ unsigned int key_of(float f) {
    unsigned int u = __float_as_uint(f);
    u ^= (u & 0x80000000u) ? 0xFFFFFFFFu : 0x80000000u;
    return ~u;
}

// Hillis-Steele exclusive block scan (all THREADS threads must call).
template <typename T>
__device__ __forceinline__ T blockExclScan(T v, T* sh) {
    int t = threadIdx.x;
    sh[t] = v;
    __syncthreads();
#pragma unroll
    for (int o = 1; o < THREADS; o <<= 1) {
        T x = (t >= o) ? sh[t - o] : (T)0;
        __syncthreads();
        sh[t] += x;
        __syncthreads();
    }
    T r = sh[t] - v;
    __syncthreads();
    return r;
}

// ---------------- histograms ----------------
__global__ void __launch_bounds__(THREADS) hist0K(const float* __restrict__ target) {
    __shared__ unsigned int h[RDX];
    int t = threadIdx.x;
    h[t] = 0;
    __syncthreads();
    int base = blockIdx.x * TILE;
#pragma unroll
    for (int s = 0; s < ITEMS; s++) {
        unsigned int k = key_of(target[base + t + s * THREADS]);
        atomicAdd(&h[k & 0xFFu], 1u);
    }
    __syncthreads();
    g_hist[(unsigned)t * NBLK + blockIdx.x] = h[t];
}

template <int PASS>
__global__ void __launch_bounds__(THREADS) histPK() {
    __shared__ unsigned int h[RDX];
    const unsigned long long* in = (PASS == 2) ? g_bufB : g_bufA;
    const int shift = 32 + 8 * PASS;
    int t = threadIdx.x;
    h[t] = 0;
    __syncthreads();
    int base = blockIdx.x * TILE;
#pragma unroll
    for (int s = 0; s < ITEMS; s++) {
        unsigned int d = (unsigned int)(in[base + t + s * THREADS] >> shift) & 0xFFu;
        atomicAdd(&h[d], 1u);
    }
    __syncthreads();
    g_hist[(unsigned)t * NBLK + blockIdx.x] = h[t];
}

// Exclusive scan of per-block counts within each digit (grid = 256 digits).
__global__ void __launch_bounds__(THREADS) scanBlocksK() {
    __shared__ unsigned int sh[THREADS];
    int d = blockIdx.x, t = threadIdx.x;
    unsigned int* row = g_hist + (unsigned)d * NBLK;
    unsigned int loc[NBLK / THREADS];
    unsigned int sum = 0;
    int b0 = t * (NBLK / THREADS);
#pragma unroll
    for (int j = 0; j < NBLK / THREADS; j++) { loc[j] = row[b0 + j]; sum += loc[j]; }
    unsigned int off = blockExclScan<unsigned int>(sum, sh);
#pragma unroll
    for (int j = 0; j < NBLK / THREADS; j++) { unsigned int v = loc[j]; row[b0 + j] = off; off += v; }
    if (t == THREADS - 1) g_digTot[d] = off;
}

__global__ void __launch_bounds__(THREADS) scanDigitsK() {
    __shared__ unsigned int sh[THREADS];
    int t = threadIdx.x;
    g_digBase[t] = blockExclScan<unsigned int>(g_digTot[t], sh);
}

// ---------------- stable scatter ----------------
// PASS0: (target,pred)->bufA  PASS1: A->B  PASS2: B->A  PASS3: A->g_sp (payload)
template <int PASS>
__global__ void __launch_bounds__(THREADS) scatterK(const float* __restrict__ target,
                                                    const float* __restrict__ pred) {
    __shared__ unsigned int       wh[RDX * PADW];
    __shared__ unsigned long long stage[TILE];
    __shared__ unsigned int       delta[RDX];
    __shared__ unsigned int       scanSh[THREADS];

    const unsigned long long* in  = (PASS == 2) ? g_bufB : g_bufA;
    unsigned long long*       out = (PASS == 1) ? g_bufB : g_bufA;
    const int shift = 32 + 8 * PASS;

    int t = threadIdx.x, lane = t & 31, w = t >> 5;
    int base = blockIdx.x * TILE + w * WCHUNK + lane;

    for (int i = t; i < RDX * PADW; i += THREADS) wh[i] = 0;
    __syncthreads();

    // Phase 1: load + per-warp digit counts (memory order = (s, lane))
    unsigned long long items[ITEMS];
#pragma unroll
    for (int s = 0; s < ITEMS; s++) {
        int p = base + s * 32;
        unsigned long long e;
        if (PASS == 0) {
            e = (((unsigned long long)key_of(target[p])) << 32)
              | (unsigned long long)__float_as_uint(pred[p]);
        } else {
            e = in[p];
        }
        items[s] = e;
        unsigned int d = (unsigned int)(e >> shift) & 0xFFu;
        unsigned int mask = __match_any_sync(0xffffffffu, d);
        if (lane == (__ffs(mask) - 1)) wh[d * PADW + w] += __popc(mask);
        __syncwarp();
    }
    __syncthreads();

    // Phase 2: exclusive scan over (digit, warp); thread t == digit t.
    {
        unsigned int sum = 0, loc[NWARP];
#pragma unroll
        for (int j = 0; j < NWARP; j++) { loc[j] = wh[t * PADW + j]; sum += loc[j]; }
        unsigned int excl = blockExclScan<unsigned int>(sum, scanSh);
        delta[t] = g_digBase[t] + g_hist[(unsigned)t * NBLK + blockIdx.x] - excl;
        unsigned int off = excl;
#pragma unroll
        for (int j = 0; j < NWARP; j++) { unsigned int v = loc[j]; wh[t * PADW + j] = off; off += v; }
    }
    __syncthreads();

    // Phase 3: stable rank into shared staging
#pragma unroll
    for (int s = 0; s < ITEMS; s++) {
        unsigned int d = (unsigned int)(items[s] >> shift) & 0xFFu;
        unsigned int mask = __match_any_sync(0xffffffffu, d);
        unsigned int b_ = wh[d * PADW + w];
        __syncwarp();
        if (lane == (__ffs(mask) - 1)) wh[d * PADW + w] = b_ + __popc(mask);
        __syncwarp();
        unsigned int rank = b_ + __popc(mask & ((1u << lane) - 1u));
        stage[rank] = items[s];
    }
    __syncthreads();

    // Phase 4: contiguous digit runs -> coalesced global writes
#pragma unroll
    for (int s = 0; s < ITEMS; s++) {
        int idx = t + s * THREADS;
        unsigned long long e = stage[idx];
        unsigned int d = (unsigned int)(e >> shift) & 0xFFu;
        unsigned int g = delta[d] + (unsigned int)idx;
        if (PASS == 3) g_sp[g] = __uint_as_float((unsigned int)e);
        else           out[g] = e;
    }
}

// ---------------- pair phase ----------------
// Pair k: left = sp[HALF-1-k], right = sp[HALF+k]; window sums = prefix over k.
__global__ void __launch_bounds__(PT) pairSumsK() {
    __shared__ double shP[PT], shM[PT];
    int t = threadIdx.x;
    int k0 = blockIdx.x * PTILE + t * PI;
    const float* R  = g_sp + HALF + k0;
    const float* Lf = g_sp + HALF - 1 - k0;
    float sp_ = 0.f, sm_ = 0.f;
#pragma unroll
    for (int s = 0; s < PI; s++) {
        float xr = R[s], xl = Lf[-s];
        sp_ += expf(xr) + expf(xl);
        sm_ += expf(-xr) + expf(-xl);
    }
    shP[t] = (double)sp_; shM[t] = (double)sm_;
    __syncthreads();
    for (int o = PT / 2; o > 0; o >>= 1) {
        if (t < o) { shP[t] += shP[t + o]; shM[t] += shM[t + o]; }
        __syncthreads();
    }
    if (t == 0) { g_bsP[blockIdx.x] = shP[0]; g_bsM[blockIdx.x] = shM[0]; }
}

__global__ void __launch_bounds__(1024) pairScanK() {
    __shared__ double sh[1024];
    int t = threadIdx.x;
    double v = g_bsP[t];
    sh[t] = v; __syncthreads();
    for (int o = 1; o < 1024; o <<= 1) {
        double x = (t >= o) ? sh[t - o] : 0.0;
        __syncthreads(); sh[t] += x; __syncthreads();
    }
    g_bsP[t] = sh[t] - v;
    __syncthreads();
    double w = g_bsM[t];
    sh[t] = w; __syncthreads();
    for (int o = 1; o < 1024; o <<= 1) {
        double x = (t >= o) ? sh[t - o] : 0.0;
        __syncthreads(); sh[t] += x; __syncthreads();
    }
    g_bsM[t] = sh[t] - w;
}

__global__ void __launch_bounds__(PT) pairTermK() {
    __shared__ double shA[PT], shB[PT];
    int t = threadIdx.x;
    int k0 = blockIdx.x * PTILE + t * PI;
    const float* R  = g_sp + HALF + k0;
    const float* Lf = g_sp + HALF - 1 - k0;

    float runP[PI], runM[PI];
    float rp = 0.f, rm = 0.f;
#pragma unroll
    for (int s = 0; s < PI; s++) {
        float xr = R[s], xl = Lf[-s];
        rp += expf(xr) + expf(xl);
        rm += expf(-xr) + expf(-xl);
        runP[s] = rp; runM[s] = rm;
    }
    double totP = (double)rp, totM = (double)rm;
    shA[t] = totP; shB[t] = totM;
    __syncthreads();
    for (int o = 1; o < PT; o <<= 1) {
        double a = (t >= o) ? shA[t - o] : 0.0;
        double b = (t >= o) ? shB[t - o] : 0.0;
        __syncthreads();
        shA[t] += a; shB[t] += b;
        __syncthreads();
    }
    float bP = (float)(g_bsP[blockIdx.x] + shA[t] - totP);
    float bM = (float)(g_bsM[blockIdx.x] + shB[t] - totM);
    __syncthreads();

    float tsum = 0.f;
#pragma unroll
    for (int s = 0; s < PI; s++) {
        float xr = R[s], xl = Lf[-s];          // L1 hits
        float Sp = bP + runP[s];
        float Sm = bM + runM[s];
        float L  = 2.0f * (float)(k0 + s + 1);
        float den = Sp * Sm - L;               // den >= L(L-1): no cancellation
        tsum += logf(den) - (xl - xr);
    }
    shA[t] = (double)tsum;
    __syncthreads();
    for (int o = PT / 2; o > 0; o >>= 1) {
        if (t < o) shA[t] += shA[t + o];
        __syncthreads();
    }
    if (t == 0) g_bt[blockIdx.x] = shA[0];
}

__global__ void __launch_bounds__(THREADS) finalK(float* __restrict__ out) {
    __shared__ double sh[THREADS];
    int t = threadIdx.x;
    double s = 0.0;
    for (int j = t; j < PNB; j += THREADS) s += g_bt[j];
    sh[t] = s;
    __syncthreads();
    for (int o = THREADS / 2; o > 0; o >>= 1) {
        if (t < o) sh[t] += sh[t + o];
        __syncthreads();
    }
    if (t == 0) out[0] = (float)sh[0];
}

extern "C" void kernel_launch(void* const* d_in, const int* in_sizes, int n_in,
                              void* d_out, int out_size) {
    const float* pred   = (const float*)d_in[0];
    const float* target = (const float*)d_in[1];
    float* out = (float*)d_out;

    // pass 0
    hist0K<<<NBLK, THREADS>>>(target);
    scanBlocksK<<<RDX, THREADS>>>();
    scanDigitsK<<<1, THREADS>>>();
    scatterK<0><<<NBLK, THREADS>>>(target, pred);
    // pass 1
    histPK<1><<<NBLK, THREADS>>>();
    scanBlocksK<<<RDX, THREADS>>>();
    scanDigitsK<<<1, THREADS>>>();
    scatterK<1><<<NBLK, THREADS>>>(nullptr, nullptr);
    // pass 2
    histPK<2><<<NBLK, THREADS>>>();
    scanBlocksK<<<RDX, THREADS>>>();
    scanDigitsK<<<1, THREADS>>>();
    scatterK<2><<<NBLK, THREADS>>>(nullptr, nullptr);
    // pass 3
    histPK<3><<<NBLK, THREADS>>>();
    scanBlocksK<<<RDX, THREADS>>>();
    scanDigitsK<<<1, THREADS>>>();
    scatterK<3><<<NBLK, THREADS>>>(nullptr, nullptr);
    // pair phase
    pairSumsK<<<PNB, PT>>>();
    pairScanK<<<1, 1024>>>();
    pairTermK<<<PNB, PT>>>();
    finalK<<<1, THREADS>>>(out);
}

// round 13
// speedup vs baseline: 1.0043x; 1.0043x over previous
#include <cuda_runtime.h>

#define NELE    8388608
#define HALF    (NELE/2)
#define THREADS 256
#define NWARP   8
#define ITEMS   16
#define TILE    4096          // THREADS*ITEMS
#define NBLK    2048          // NELE/TILE
#define RDX     256
#define WCHUNK  512           // TILE/NWARP
#define PADW    10

#define PT      256
#define PI      16
#define PTILE   4096
#define PNB     1024          // HALF/PTILE

// ---- scratch (device globals; no runtime allocation allowed) ----
__device__ unsigned long long g_bufA[NELE];
__device__ unsigned long long g_bufB[NELE];
__device__ float              g_sp[NELE];
__device__ unsigned int       g_hist[RDX * NBLK];
__device__ unsigned int       g_digTot[RDX];
__device__ unsigned int       g_digBase[RDX];
__device__ double             g_bsP[PNB];
__device__ double             g_bsM[PNB];
__device__ double             g_bt[PNB];

// Radix key: ascending order of (-target) == descending target, IEEE total order.
__device__ __forceinline__ unsigned int key_of(float f) {
    unsigned int u = __float_as_uint(f);
    u ^= (u & 0x80000000u) ? 0xFFFFFFFFu : 0x80000000u;
    return ~u;
}

// Hillis-Steele exclusive block scan (all THREADS threads must call).
template <typename T>
__device__ __forceinline__ T blockExclScan(T v, T* sh) {
    int t = threadIdx.x;
    sh[t] = v;
    __syncthreads();
#pragma unroll
    for (int o = 1; o < THREADS; o <<= 1) {
        T x = (t >= o) ? sh[t - o] : (T)0;
        __syncthreads();
        sh[t] += x;
        __syncthreads();
    }
    T r = sh[t] - v;
    __syncthreads();
    return r;
}

// ---------------- histograms ----------------
__global__ void __launch_bounds__(THREADS) hist0K(const float* __restrict__ target) {
    __shared__ unsigned int h[RDX];
    int t = threadIdx.x;
    h[t] = 0;
    __syncthreads();
    int base = blockIdx.x * TILE;
#pragma unroll
    for (int s = 0; s < ITEMS; s++) {
        unsigned int k = key_of(target[base + t + s * THREADS]);
        atomicAdd(&h[k & 0xFFu], 1u);
    }
    __syncthreads();
    g_hist[(unsigned)t * NBLK + blockIdx.x] = h[t];
}

template <int PASS>
__global__ void __launch_bounds__(THREADS) histPK() {
    __shared__ unsigned int h[RDX];
    const unsigned long long* in = (PASS == 2) ? g_bufB : g_bufA;
    const int shift = 32 + 8 * PASS;
    int t = threadIdx.x;
    h[t] = 0;
    __syncthreads();
    int base = blockIdx.x * TILE;
#pragma unroll
    for (int s = 0; s < ITEMS; s++) {
        unsigned int d = (unsigned int)(in[base + t + s * THREADS] >> shift) & 0xFFu;
        atomicAdd(&h[d], 1u);
    }
    __syncthreads();
    g_hist[(unsigned)t * NBLK + blockIdx.x] = h[t];
}

// Exclusive scan of per-block counts within each digit (grid = 256 digits).
__global__ void __launch_bounds__(THREADS) scanBlocksK() {
    __shared__ unsigned int sh[THREADS];
    int d = blockIdx.x, t = threadIdx.x;
    unsigned int* row = g_hist + (unsigned)d * NBLK;
    unsigned int loc[NBLK / THREADS];
    unsigned int sum = 0;
    int b0 = t * (NBLK / THREADS);
#pragma unroll
    for (int j = 0; j < NBLK / THREADS; j++) { loc[j] = row[b0 + j]; sum += loc[j]; }
    unsigned int off = blockExclScan<unsigned int>(sum, sh);
#pragma unroll
    for (int j = 0; j < NBLK / THREADS; j++) { unsigned int v = loc[j]; row[b0 + j] = off; off += v; }
    if (t == THREADS - 1) g_digTot[d] = off;
}

__global__ void __launch_bounds__(THREADS) scanDigitsK() {
    __shared__ unsigned int sh[THREADS];
    int t = threadIdx.x;
    g_digBase[t] = blockExclScan<unsigned int>(g_digTot[t], sh);
}

// ---------------- stable scatter ----------------
// PASS0: (target,pred)->bufA  PASS1: A->B  PASS2: B->A  PASS3: A->g_sp (payload)
template <int PASS>
__global__ void __launch_bounds__(THREADS) scatterK(const float* __restrict__ target,
                                                    const float* __restrict__ pred) {
    __shared__ unsigned int       wh[RDX * PADW];
    __shared__ unsigned long long stage[TILE];
    __shared__ unsigned int       delta[RDX];
    __shared__ unsigned int       scanSh[THREADS];

    const unsigned long long* in  = (PASS == 2) ? g_bufB : g_bufA;
    unsigned long long*       out = (PASS == 1) ? g_bufB : g_bufA;
    const int shift = 32 + 8 * PASS;

    int t = threadIdx.x, lane = t & 31, w = t >> 5;
    int base = blockIdx.x * TILE + w * WCHUNK + lane;

    for (int i = t; i < RDX * PADW; i += THREADS) wh[i] = 0;
    __syncthreads();

    // Phase 1: load + per-warp digit counts (memory order = (s, lane))
    unsigned long long items[ITEMS];
#pragma unroll
    for (int s = 0; s < ITEMS; s++) {
        int p = base + s * 32;
        unsigned long long e;
        if (PASS == 0) {
            e = (((unsigned long long)key_of(target[p])) << 32)
              | (unsigned long long)__float_as_uint(pred[p]);
        } else {
            e = in[p];
        }
        items[s] = e;
        unsigned int d = (unsigned int)(e >> shift) & 0xFFu;
        unsigned int mask = __match_any_sync(0xffffffffu, d);
        if (lane == (__ffs(mask) - 1)) wh[d * PADW + w] += __popc(mask);
        __syncwarp();
    }
    __syncthreads();

    // Phase 2: exclusive scan over (digit, warp); thread t == digit t.
    {
        unsigned int sum = 0, loc[NWARP];
#pragma unroll
        for (int j = 0; j < NWARP; j++) { loc[j] = wh[t * PADW + j]; sum += loc[j]; }
        unsigned int excl = blockExclScan<unsigned int>(sum, scanSh);
        delta[t] = g_digBase[t] + g_hist[(unsigned)t * NBLK + blockIdx.x] - excl;
        unsigned int off = excl;
#pragma unroll
        for (int j = 0; j < NWARP; j++) { unsigned int v = loc[j]; wh[t * PADW + j] = off; off += v; }
    }
    __syncthreads();

    // Phase 3: stable rank into shared staging
#pragma unroll
    for (int s = 0; s < ITEMS; s++) {
        unsigned int d = (unsigned int)(items[s] >> shift) & 0xFFu;
        unsigned int mask = __match_any_sync(0xffffffffu, d);
        unsigned int b_ = wh[d * PADW + w];
        __syncwarp();
        if (lane == (__ffs(mask) - 1)) wh[d * PADW + w] = b_ + __popc(mask);
        __syncwarp();
        unsigned int rank = b_ + __popc(mask & ((1u << lane) - 1u));
        stage[rank] = items[s];
    }
    __syncthreads();

    // Phase 4: contiguous digit runs -> coalesced global writes
#pragma unroll
    for (int s = 0; s < ITEMS; s++) {
        int idx = t + s * THREADS;
        unsigned long long e = stage[idx];
        unsigned int d = (unsigned int)(e >> shift) & 0xFFu;
        unsigned int g = delta[d] + (unsigned int)idx;
        if (PASS == 3) g_sp[g] = __uint_as_float((unsigned int)e);
        else           out[g] = e;
    }
}

// ---------------- pair phase ----------------
// Pair k: left = sp[HALF-1-k], right = sp[HALF+k]; window sums = prefix over k.
__global__ void __launch_bounds__(PT) pairSumsK() {
    __shared__ double shP[PT], shM[PT];
    int t = threadIdx.x;
    int k0 = blockIdx.x * PTILE + t * PI;
    const float* R  = g_sp + HALF + k0;
    const float* Lf = g_sp + HALF - 1 - k0;
    float sp_ = 0.f, sm_ = 0.f;
#pragma unroll
    for (int s = 0; s < PI; s++) {
        float xr = R[s], xl = Lf[-s];
        sp_ += expf(xr) + expf(xl);
        sm_ += expf(-xr) + expf(-xl);
    }
    shP[t] = (double)sp_; shM[t] = (double)sm_;
    __syncthreads();
    for (int o = PT / 2; o > 0; o >>= 1) {
        if (t < o) { shP[t] += shP[t + o]; shM[t] += shM[t + o]; }
        __syncthreads();
    }
    if (t == 0) { g_bsP[blockIdx.x] = shP[0]; g_bsM[blockIdx.x] = shM[0]; }
}

__global__ void __launch_bounds__(1024) pairScanK() {
    __shared__ double sh[1024];
    int t = threadIdx.x;
    double v = g_bsP[t];
    sh[t] = v; __syncthreads();
    for (int o = 1; o < 1024; o <<= 1) {
        double x = (t >= o) ? sh[t - o] : 0.0;
        __syncthreads(); sh[t] += x; __syncthreads();
    }
    g_bsP[t] = sh[t] - v;
    __syncthreads();
    double w = g_bsM[t];
    sh[t] = w; __syncthreads();
    for (int o = 1; o < 1024; o <<= 1) {
        double x = (t >= o) ? sh[t - o] : 0.0;
        __syncthreads(); sh[t] += x; __syncthreads();
    }
    g_bsM[t] = sh[t] - w;
}

__global__ void __launch_bounds__(PT) pairTermK() {
    __shared__ double shA[PT], shB[PT];
    int t = threadIdx.x;
    int k0 = blockIdx.x * PTILE + t * PI;
    const float* R  = g_sp + HALF + k0;
    const float* Lf = g_sp + HALF - 1 - k0;

    float runP[PI], runM[PI];
    float rp = 0.f, rm = 0.f;
#pragma unroll
    for (int s = 0; s < PI; s++) {
        float xr = R[s], xl = Lf[-s];
        rp += expf(xr) + expf(xl);
        rm += expf(-xr) + expf(-xl);
        runP[s] = rp; runM[s] = rm;
    }
    double totP = (double)rp, totM = (double)rm;
    shA[t] = totP; shB[t] = totM;
    __syncthreads();
    for (int o = 1; o < PT; o <<= 1) {
        double a = (t >= o) ? shA[t - o] : 0.0;
        double b = (t >= o) ? shB[t - o] : 0.0;
        __syncthreads();
        shA[t] += a; shB[t] += b;
        __syncthreads();
    }
    float bP = (float)(g_bsP[blockIdx.x] + shA[t] - totP);
    float bM = (float)(g_bsM[blockIdx.x] + shB[t] - totM);
    __syncthreads();

    float tsum = 0.f;
#pragma unroll
    for (int s = 0; s < PI; s++) {
        float xr = R[s], xl = Lf[-s];          // L1 hits
        float Sp = bP + runP[s];
        float Sm = bM + runM[s];
        float L  = 2.0f * (float)(k0 + s + 1);
        float den = Sp * Sm - L;               // den >= L(L-1): no cancellation
        tsum += logf(den) - (xl - xr);
    }
    shA[t] = (double)tsum;
    __syncthreads();
    for (int o = PT / 2; o > 0; o >>= 1) {
        if (t < o) shA[t] += shA[t + o];
        __syncthreads();
    }
    if (t == 0) g_bt[blockIdx.x] = shA[0];
}

__global__ void __launch_bounds__(THREADS) finalK(float* __restrict__ out) {
    __shared__ double sh[THREADS];
    int t = threadIdx.x;
    double s = 0.0;
    for (int j = t; j < PNB; j += THREADS) s += g_bt[j];
    sh[t] = s;
    __syncthreads();
    for (int o = THREADS / 2; o > 0; o >>= 1) {
        if (t < o) sh[t] += sh[t + o];
        __syncthreads();
    }
    if (t == 0) out[0] = (float)sh[0];
}

extern "C" void kernel_launch(void* const* d_in, const int* in_sizes, int n_in,
                              void* d_out, int out_size) {
    const float* pred   = (const float*)d_in[0];
    const float* target = (const float*)d_in[1];
    float* out = (float*)d_out;

    // pass 0
    hist0K<<<NBLK, THREADS>>>(target);
    scanBlocksK<<<RDX, THREADS>>>();
    scanDigitsK<<<1, THREADS>>>();
    scatterK<0><<<NBLK, THREADS>>>(target, pred);
    // pass 1
    histPK<1><<<NBLK, THREADS>>>();
    scanBlocksK<<<RDX, THREADS>>>();
    scanDigitsK<<<1, THREADS>>>();
    scatterK<1><<<NBLK, THREADS>>>(nullptr, nullptr);
    // pass 2
    histPK<2><<<NBLK, THREADS>>>();
    scanBlocksK<<<RDX, THREADS>>>();
    scanDigitsK<<<1, THREADS>>>();
    scatterK<2><<<NBLK, THREADS>>>(nullptr, nullptr);
    // pass 3
    histPK<3><<<NBLK, THREADS>>>();
    scanBlocksK<<<RDX, THREADS>>>();
    scanDigitsK<<<1, THREADS>>>();
    scatterK<3><<<NBLK, THREADS>>>(nullptr, nullptr);
    // pair phase
    pairSumsK<<<PNB, PT>>>();
    pairScanK<<<1, 1024>>>();
    pairTermK<<<PNB, PT>>>();
    finalK<<<1, THREADS>>>(out);
}